// round 12
// baseline (speedup 1.0000x reference)
#include <cuda_runtime.h>
#include <math.h>

#define NB   64
#define NN   1024
#define FIN  14
#define NH   128
#define NTOT (NB*NN)        /* 65536 */
#define NE   (NTOT*8)       /* 524288 */
#define KP1  820
#define KP2  656

/* ---------------- scratch (device globals; no allocs allowed) ---------------- */
__device__ int                    g_deg[NTOT];
__device__ int                    g_rows[NTOT + 1];
__device__ int                    g_cur[NTOT];
__device__ int                    g_esrc[NE];
__device__ __align__(16) float    g_h1[NTOT * NH];
__device__ __align__(16) float    g_agg2[NTOT * NH];
__device__ __align__(16) float    g_h2[NTOT * NH];
__device__ float                  g_logit1[NTOT];
__device__ float                  g_logit2[NTOT];
__device__ float                  g_scale1[NTOT];
__device__ float                  g_scale2[NTOT];
__device__ int                    g_kept1[NTOT];
__device__ int                    g_kept2[NTOT];
__device__ int                    g_rank1[NTOT];   /* pool1 top-k rank (pool2 tie-break) */

/* HW tanh: tanh.approx.f32 (MUFU.TANH) — what XLA GPU emits for f32 tanh.
   Max rel err ~2^-11; using the SAME instruction makes vals bit-identical
   to the reference. */
__device__ __forceinline__ float tanh_hw(float x) {
    float y;
    asm("tanh.approx.f32 %0, %1;" : "=f"(y) : "f"(x));
    return y;
}

/* ---------------- CSR build ---------------- */
__global__ void k_zero_deg() {
    int i = blockIdx.x * blockDim.x + threadIdx.x;
    if (i < NTOT) g_deg[i] = 0;
}

__global__ void k_hist(const int* __restrict__ dst) {
    int e = blockIdx.x * blockDim.x + threadIdx.x;
    if (e < NE) atomicAdd(&g_deg[dst[e]], 1);
}

__global__ void k_scan() {
    __shared__ int ssum[1024];
    int t = threadIdx.x;
    int base = t * 64;
    int s = 0;
    for (int i = 0; i < 64; i++) s += g_deg[base + i];
    ssum[t] = s;
    __syncthreads();
    for (int off = 1; off < 1024; off <<= 1) {
        int v = 0;
        if (t >= off) v = ssum[t - off];
        __syncthreads();
        if (t >= off) ssum[t] += v;
        __syncthreads();
    }
    int run = ssum[t] - s;
    for (int i = 0; i < 64; i++) {
        int d = g_deg[base + i];
        g_rows[base + i] = run;
        g_cur[base + i]  = run;
        run += d;
    }
    if (t == 1023) g_rows[NTOT] = run;
}

__global__ void k_scatter(const int* __restrict__ src, const int* __restrict__ dst) {
    int e = blockIdx.x * blockDim.x + threadIdx.x;
    if (e < NE) {
        int p = atomicAdd(&g_cur[dst[e]], 1);
        g_esrc[p] = src[e];
    }
}

/* ---------------- conv1: warp per node, pure fp32 ---------------- */
__global__ void __launch_bounds__(256)
k_conv1(const float* __restrict__ x,
        const float* __restrict__ W1rel, const float* __restrict__ b1,
        const float* __restrict__ W1root, const float* __restrict__ p1w) {
    __shared__ float sWrel[NH * FIN];
    __shared__ float sWroot[NH * FIN];
    __shared__ float sb[NH];
    __shared__ float spw[NH];
    __shared__ float sAgg[8][FIN];
    __shared__ float sXv[8][FIN];

    int tid = threadIdx.x;
    for (int i = tid; i < NH * FIN; i += 256) {
        sWrel[i]  = W1rel[i];
        sWroot[i] = W1root[i];
    }
    if (tid < NH) { sb[tid] = b1[tid]; spw[tid] = p1w[tid]; }
    __syncthreads();

    int w    = tid >> 5;
    int lane = tid & 31;
    int v    = blockIdx.x * 8 + w;

    int rs = g_rows[v], re = g_rows[v + 1];
    if (lane < FIN) {
        float a  = 0.f;
        float xv = x[v * FIN + lane];
        for (int i = rs; i < re; i++) {
            int s = g_esrc[i];
            a += x[s * FIN + lane];
        }
        sAgg[w][lane] = a;
        sXv[w][lane]  = xv;
    }
    __syncwarp();

    float lp = 0.f;
    float hj[4];
#pragma unroll
    for (int jj = 0; jj < 4; jj++) {
        int j = lane * 4 + jj;
        float acc = sb[j];
#pragma unroll
        for (int k = 0; k < FIN; k++)
            acc += sAgg[w][k] * sWrel[j * FIN + k] + sXv[w][k] * sWroot[j * FIN + k];
        acc = fmaxf(acc, 0.f);
        hj[jj] = acc;
        lp += acc * spw[j];
    }
    *(float4*)&g_h1[v * NH + lane * 4] = make_float4(hj[0], hj[1], hj[2], hj[3]);
#pragma unroll
    for (int o = 16; o > 0; o >>= 1) lp += __shfl_xor_sync(0xffffffffu, lp, o);
    if (lane == 0) g_logit1[v] = lp;
}

/* ------- per-graph top-K: sort on (tanh.approx score DESC, tie-key ASC) -----
   Matches jax.lax.top_k with lowest-index-first ties. Tie key:
   pool1 = node index; pool2 = pool1 rank (pooled row order).              */
__device__ __forceinline__ bool pair_before(float va, int ia, float vb, int ib) {
    return (va > vb) || (va == vb && ia < ib);
}

__global__ void __launch_bounds__(1024)
k_pool(const float* __restrict__ logitArr, const int* __restrict__ valid,
       const int* __restrict__ keyIn, const float* __restrict__ w,
       int* __restrict__ kept, float* __restrict__ scale,
       int* __restrict__ rankOut, int K) {
    __shared__ float sv[NN];
    __shared__ int   si[NN];
    __shared__ float red[128];
    __shared__ float snorm;

    int t = threadIdx.x, g = blockIdx.x;

    /* fp32 norm (matches jnp.linalg.norm on f32) */
    if (t < 128) { float w0 = w[t]; red[t] = w0 * w0; }
    __syncthreads();
    if (t < 64) red[t] += red[t + 64];
    __syncthreads();
    if (t < 32) {
        float s = red[t] + red[t + 32];
#pragma unroll
        for (int o = 16; o > 0; o >>= 1) s += __shfl_xor_sync(0xffffffffu, s, o);
        if (t == 0) snorm = __fsqrt_rn(s);
    }
    __syncthreads();

    int orig = g * NN + t;
    float scv = -3.0f;                     /* below any tanh value */
    int   key;
    if (valid == nullptr || valid[orig]) {
        scv = tanh_hw(__fdiv_rn(logitArr[orig], snorm));
        key = keyIn ? keyIn[orig] : t;
    } else {
        key = 500000 + t;                  /* after all valid keys */
    }
    sv[t] = scv;
    si[t] = key * 2048 + t;                /* pack: tie-key | orig slot */
    __syncthreads();

    for (int k = 2; k <= NN; k <<= 1) {
        for (int j = k >> 1; j > 0; j >>= 1) {
            int ixj = t ^ j;
            if (ixj > t) {
                float va = sv[t], vb = sv[ixj];
                int   ia = si[t], ib = si[ixj];
                bool up = ((t & k) == 0);
                bool swp = up ? pair_before(vb, ib, va, ia)
                              : pair_before(va, ia, vb, ib);
                if (swp) { sv[t] = vb; si[t] = ib; sv[ixj] = va; si[ixj] = ia; }
            }
            __syncthreads();
        }
    }

    int oidx = g * NN + (si[t] & 2047);
    if (t < K) { kept[oidx] = 1; scale[oidx] = sv[t]; }   /* scale = top_k val */
    else       { kept[oidx] = 0; scale[oidx] = 0.f; }
    if (rankOut) rankOut[oidx] = t;
}

/* ---------------- readout: mean & max over kept, per graph ---------------- */
__global__ void __launch_bounds__(128)
k_readout(const float* __restrict__ h, const int* __restrict__ kept,
          const float* __restrict__ scale, float* __restrict__ out,
          float invK, int accumulate) {
    __shared__ float ssc[NN];
    __shared__ int   skp[NN];
    int g = blockIdx.x, j = threadIdx.x;
    for (int i = j; i < NN; i += 128) {
        ssc[i] = scale[g * NN + i];
        skp[i] = kept[g * NN + i];
    }
    __syncthreads();
    float sum = 0.f, mx = -INFINITY;
#pragma unroll 4
    for (int v = 0; v < NN; v++) {
        if (skp[v]) {
            float hv = h[(g * NN + v) * NH + j] * ssc[v];
            sum += hv;
            mx = fmaxf(mx, hv);
        }
    }
    float o0 = sum * invK;
    if (accumulate) {
        out[g * 256 + j]       += o0;
        out[g * 256 + 128 + j] += mx;
    } else {
        out[g * 256 + j]       = o0;
        out[g * 256 + 128 + j] = mx;
    }
}

/* ---------------- conv2 aggregation gather (fp32) ---------------- */
__global__ void __launch_bounds__(256)
k_gather2() {
    int tid  = threadIdx.x;
    int w    = tid >> 5;
    int lane = tid & 31;
    int v    = blockIdx.x * 8 + w;
    if (!g_kept1[v]) return;
    int rs = g_rows[v], re = g_rows[v + 1];
    int l4 = lane * 4;
    float4 a = make_float4(0.f, 0.f, 0.f, 0.f);
    for (int i = rs; i < re; i++) {
        int s = g_esrc[i];
        if (g_kept1[s]) {
            float sc = g_scale1[s];
            float4 hv = *(const float4*)&g_h1[s * NH + l4];
            a.x += hv.x * sc; a.y += hv.y * sc;
            a.z += hv.z * sc; a.w += hv.w * sc;
        }
    }
    *(float4*)&g_agg2[v * NH + l4] = a;
}

/* ---- conv2 GEMM (pure fp32): h2 = relu([agg2|h1*s1]@[W2rel;W2root]^T + b2) */
#define GM  64
#define GKC 32
__global__ void __launch_bounds__(256)
k_gemm2(const float* __restrict__ W2rel, const float* __restrict__ b2,
        const float* __restrict__ W2root) {
    __shared__ __align__(16) float As[GKC][GM];
    __shared__ __align__(16) float Ws[GKC][132];
    __shared__ float sb2[NH];

    int tid = threadIdx.x;
    int m0  = blockIdx.x * GM;
    if (tid < NH) sb2[tid] = b2[tid];

    int tx = tid & 15;
    int ty = tid >> 4;

    float acc[4][8];
#pragma unroll
    for (int i = 0; i < 4; i++)
#pragma unroll
        for (int j = 0; j < 8; j++) acc[i][j] = 0.f;

    for (int kc = 0; kc < 2 * NH; kc += GKC) {
#pragma unroll
        for (int r = 0; r < 2; r++) {
            int id = tid + r * 256;
            int m  = id >> 3;
            int k4 = id & 7;
            int kk = kc + k4 * 4;
            int node = m0 + m;
            float4 val;
            if (kk < NH) {
                val = *(const float4*)&g_agg2[node * NH + kk];
            } else {
                float sc = g_kept1[node] ? g_scale1[node] : 0.f;
                float4 h = *(const float4*)&g_h1[node * NH + (kk - NH)];
                val = make_float4(h.x * sc, h.y * sc, h.z * sc, h.w * sc);
            }
            int kl = k4 * 4;
            As[kl + 0][m] = val.x; As[kl + 1][m] = val.y;
            As[kl + 2][m] = val.z; As[kl + 3][m] = val.w;
        }
#pragma unroll
        for (int r = 0; r < 4; r++) {
            int id = tid + r * 256;
            int j  = id >> 3;
            int k4 = id & 7;
            int kk = kc + k4 * 4;
            const float* Wsrc = (kk < NH) ? W2rel : W2root;
            int kw = (kk < NH) ? kk : (kk - NH);
            float4 val = *(const float4*)&Wsrc[j * NH + kw];
            int kl = k4 * 4;
            Ws[kl + 0][j] = val.x; Ws[kl + 1][j] = val.y;
            Ws[kl + 2][j] = val.z; Ws[kl + 3][j] = val.w;
        }
        __syncthreads();
#pragma unroll
        for (int k = 0; k < GKC; k++) {
            float4 a4 = *(const float4*)&As[k][ty * 4];
            float4 w0 = *(const float4*)&Ws[k][tx * 4];
            float4 w1 = *(const float4*)&Ws[k][64 + tx * 4];
            float am[4] = {a4.x, a4.y, a4.z, a4.w};
            float wv[8] = {w0.x, w0.y, w0.z, w0.w, w1.x, w1.y, w1.z, w1.w};
#pragma unroll
            for (int mi = 0; mi < 4; mi++)
#pragma unroll
                for (int ji = 0; ji < 8; ji++)
                    acc[mi][ji] += am[mi] * wv[ji];
        }
        __syncthreads();
    }

#pragma unroll
    for (int mi = 0; mi < 4; mi++) {
        int node = m0 + ty * 4 + mi;
        float4 o0, o1;
        o0.x = fmaxf(acc[mi][0] + sb2[tx * 4 + 0], 0.f);
        o0.y = fmaxf(acc[mi][1] + sb2[tx * 4 + 1], 0.f);
        o0.z = fmaxf(acc[mi][2] + sb2[tx * 4 + 2], 0.f);
        o0.w = fmaxf(acc[mi][3] + sb2[tx * 4 + 3], 0.f);
        o1.x = fmaxf(acc[mi][4] + sb2[64 + tx * 4 + 0], 0.f);
        o1.y = fmaxf(acc[mi][5] + sb2[64 + tx * 4 + 1], 0.f);
        o1.z = fmaxf(acc[mi][6] + sb2[64 + tx * 4 + 2], 0.f);
        o1.w = fmaxf(acc[mi][7] + sb2[64 + tx * 4 + 3], 0.f);
        *(float4*)&g_h2[node * NH + tx * 4]      = o0;
        *(float4*)&g_h2[node * NH + 64 + tx * 4] = o1;
    }
}

/* ---------------- logit2: warp per node (fp32) ---------------- */
__global__ void __launch_bounds__(256)
k_logit2(const float* __restrict__ p2w) {
    int tid  = threadIdx.x;
    int w    = tid >> 5;
    int lane = tid & 31;
    int v    = blockIdx.x * 8 + w;
    if (!g_kept1[v]) return;
    float4 h  = *(const float4*)&g_h2[v * NH + lane * 4];
    float4 ww = *(const float4*)&p2w[lane * 4];
    float lp = h.x * ww.x + h.y * ww.y + h.z * ww.z + h.w * ww.w;
#pragma unroll
    for (int o = 16; o > 0; o >>= 1) lp += __shfl_xor_sync(0xffffffffu, lp, o);
    if (lane == 0) g_logit2[v] = lp;
}

/* ---------------- launch ---------------- */
extern "C" void kernel_launch(void* const* d_in, const int* in_sizes, int n_in,
                              void* d_out, int out_size) {
    const float* x      = (const float*)d_in[0];
    const int*   ei     = (const int*)d_in[1];
    /* d_in[2] = batch (unused) */
    const float* W1rel  = (const float*)d_in[3];
    const float* b1     = (const float*)d_in[4];
    const float* W1root = (const float*)d_in[5];
    const float* p1w    = (const float*)d_in[6];
    const float* W2rel  = (const float*)d_in[7];
    const float* b2     = (const float*)d_in[8];
    const float* W2root = (const float*)d_in[9];
    const float* p2w    = (const float*)d_in[10];
    float* out = (float*)d_out;

    const int* src = ei;
    const int* dst = ei + NE;

    float* d_logit1;  cudaGetSymbolAddress((void**)&d_logit1, g_logit1);
    float* d_logit2;  cudaGetSymbolAddress((void**)&d_logit2, g_logit2);
    float* d_scale1;  cudaGetSymbolAddress((void**)&d_scale1, g_scale1);
    float* d_scale2;  cudaGetSymbolAddress((void**)&d_scale2, g_scale2);
    int*   d_kept1;   cudaGetSymbolAddress((void**)&d_kept1,  g_kept1);
    int*   d_kept2;   cudaGetSymbolAddress((void**)&d_kept2,  g_kept2);
    int*   d_rank1;   cudaGetSymbolAddress((void**)&d_rank1,  g_rank1);
    float* d_h1;      cudaGetSymbolAddress((void**)&d_h1,     g_h1);
    float* d_h2;      cudaGetSymbolAddress((void**)&d_h2,     g_h2);

    /* CSR build */
    k_zero_deg<<<NTOT / 256, 256>>>();
    k_hist<<<NE / 256, 256>>>(dst);
    k_scan<<<1, 1024>>>();
    k_scatter<<<NE / 256, 256>>>(src, dst);

    /* layer 1: rank + scale via tanh.approx; tie-break = node index */
    k_conv1<<<NTOT / 8, 256>>>(x, W1rel, b1, W1root, p1w);
    k_pool<<<NB, 1024>>>(d_logit1, (const int*)nullptr, (const int*)nullptr,
                         p1w, d_kept1, d_scale1, d_rank1, KP1);
    k_readout<<<NB, 128>>>(d_h1, d_kept1, d_scale1, out, 1.0f / (float)KP1, 0);

    /* layer 2: valid = kept1, tie-break = pool1 rank (pooled row order) */
    k_gather2<<<NTOT / 8, 256>>>();
    k_gemm2<<<NTOT / GM, 256>>>(W2rel, b2, W2root);
    k_logit2<<<NTOT / 8, 256>>>(p2w);
    k_pool<<<NB, 1024>>>(d_logit2, d_kept1, d_rank1,
                         p2w, d_kept2, d_scale2, (int*)nullptr, KP2);
    k_readout<<<NB, 128>>>(d_h2, d_kept2, d_scale2, out, 1.0f / (float)KP2, 1);
}

// round 13
// speedup vs baseline: 1.1542x; 1.1542x over previous
#include <cuda_runtime.h>
#include <math.h>

#define NB   64
#define NN   1024
#define FIN  14
#define NH   128
#define NTOT (NB*NN)        /* 65536 */
#define NE   (NTOT*8)       /* 524288 */
#define KP1  820
#define KP2  656

/* ---------------- scratch (device globals; no allocs allowed) ---------------- */
__device__ int                    g_deg[NTOT];
__device__ int                    g_rows[NTOT + 1];
__device__ int                    g_cur[NTOT];
__device__ int                    g_esrc[NE];
__device__ __align__(16) float    g_h1[NTOT * NH];
__device__ __align__(16) float    g_agg2[NTOT * NH];
__device__ __align__(16) float    g_h2[NTOT * NH];
__device__ float                  g_logit1[NTOT];
__device__ float                  g_logit2[NTOT];
__device__ float                  g_scale1[NTOT];
__device__ float                  g_scale2[NTOT];
__device__ int                    g_kept1[NTOT];
__device__ int                    g_kept2[NTOT];
__device__ int                    g_rank1[NTOT];

/* HW tanh: tanh.approx.f32 (MUFU.TANH) — matches the reference bit-for-bit. */
__device__ __forceinline__ float tanh_hw(float x) {
    float y;
    asm("tanh.approx.f32 %0, %1;" : "=f"(y) : "f"(x));
    return y;
}

/* ---------------- CSR build ---------------- */
__global__ void k_zero_deg() {
    int i = blockIdx.x * blockDim.x + threadIdx.x;
    if (i < NTOT) g_deg[i] = 0;
}

__global__ void k_hist(const int* __restrict__ dst) {
    int e = blockIdx.x * blockDim.x + threadIdx.x;
    if (e < NE) atomicAdd(&g_deg[dst[e]], 1);
}

__global__ void k_scan() {
    __shared__ int ssum[1024];
    int t = threadIdx.x;
    int base = t * 64;
    int s = 0;
    for (int i = 0; i < 64; i++) s += g_deg[base + i];
    ssum[t] = s;
    __syncthreads();
    for (int off = 1; off < 1024; off <<= 1) {
        int v = 0;
        if (t >= off) v = ssum[t - off];
        __syncthreads();
        if (t >= off) ssum[t] += v;
        __syncthreads();
    }
    int run = ssum[t] - s;
    for (int i = 0; i < 64; i++) {
        int d = g_deg[base + i];
        g_rows[base + i] = run;
        g_cur[base + i]  = run;
        run += d;
    }
    if (t == 1023) g_rows[NTOT] = run;
}

__global__ void k_scatter(const int* __restrict__ src, const int* __restrict__ dst) {
    int e = blockIdx.x * blockDim.x + threadIdx.x;
    if (e < NE) {
        int p = atomicAdd(&g_cur[dst[e]], 1);
        g_esrc[p] = src[e];
    }
}

/* ---------------- conv1: warp per node, pure fp32 ---------------- */
__global__ void __launch_bounds__(256)
k_conv1(const float* __restrict__ x,
        const float* __restrict__ W1rel, const float* __restrict__ b1,
        const float* __restrict__ W1root, const float* __restrict__ p1w) {
    __shared__ float sWrel[NH * FIN];
    __shared__ float sWroot[NH * FIN];
    __shared__ float sb[NH];
    __shared__ float spw[NH];
    __shared__ float sAgg[8][FIN];
    __shared__ float sXv[8][FIN];

    int tid = threadIdx.x;
    for (int i = tid; i < NH * FIN; i += 256) {
        sWrel[i]  = W1rel[i];
        sWroot[i] = W1root[i];
    }
    if (tid < NH) { sb[tid] = b1[tid]; spw[tid] = p1w[tid]; }
    __syncthreads();

    int w    = tid >> 5;
    int lane = tid & 31;
    int v    = blockIdx.x * 8 + w;

    int rs = g_rows[v], re = g_rows[v + 1];
    if (lane < FIN) {
        float a  = 0.f;
        float xv = x[v * FIN + lane];
        for (int i = rs; i < re; i++) {
            int s = g_esrc[i];
            a += x[s * FIN + lane];
        }
        sAgg[w][lane] = a;
        sXv[w][lane]  = xv;
    }
    __syncwarp();

    float lp = 0.f;
    float hj[4];
#pragma unroll
    for (int jj = 0; jj < 4; jj++) {
        int j = lane * 4 + jj;
        float acc = sb[j];
#pragma unroll
        for (int k = 0; k < FIN; k++)
            acc += sAgg[w][k] * sWrel[j * FIN + k] + sXv[w][k] * sWroot[j * FIN + k];
        acc = fmaxf(acc, 0.f);
        hj[jj] = acc;
        lp += acc * spw[j];
    }
    *(float4*)&g_h1[v * NH + lane * 4] = make_float4(hj[0], hj[1], hj[2], hj[3]);
#pragma unroll
    for (int o = 16; o > 0; o >>= 1) lp += __shfl_xor_sync(0xffffffffu, lp, o);
    if (lane == 0) g_logit1[v] = lp;
}

/* ------- per-graph top-K: sort on (tanh.approx score DESC, tie-key ASC) ----- */
__device__ __forceinline__ bool pair_before(float va, int ia, float vb, int ib) {
    return (va > vb) || (va == vb && ia < ib);
}

__global__ void __launch_bounds__(1024)
k_pool(const float* __restrict__ logitArr, const int* __restrict__ valid,
       const int* __restrict__ keyIn, const float* __restrict__ w,
       int* __restrict__ kept, float* __restrict__ scale,
       int* __restrict__ rankOut, int K) {
    __shared__ float sv[NN];
    __shared__ int   si[NN];
    __shared__ float red[128];
    __shared__ float snorm;

    int t = threadIdx.x, g = blockIdx.x;

    if (t < 128) { float w0 = w[t]; red[t] = w0 * w0; }
    __syncthreads();
    if (t < 64) red[t] += red[t + 64];
    __syncthreads();
    if (t < 32) {
        float s = red[t] + red[t + 32];
#pragma unroll
        for (int o = 16; o > 0; o >>= 1) s += __shfl_xor_sync(0xffffffffu, s, o);
        if (t == 0) snorm = __fsqrt_rn(s);
    }
    __syncthreads();

    int orig = g * NN + t;
    float scv = -3.0f;
    int   key;
    if (valid == nullptr || valid[orig]) {
        scv = tanh_hw(__fdiv_rn(logitArr[orig], snorm));
        key = keyIn ? keyIn[orig] : t;
    } else {
        key = 500000 + t;
    }
    sv[t] = scv;
    si[t] = key * 2048 + t;
    __syncthreads();

    for (int k = 2; k <= NN; k <<= 1) {
        for (int j = k >> 1; j > 0; j >>= 1) {
            int ixj = t ^ j;
            if (ixj > t) {
                float va = sv[t], vb = sv[ixj];
                int   ia = si[t], ib = si[ixj];
                bool up = ((t & k) == 0);
                bool swp = up ? pair_before(vb, ib, va, ia)
                              : pair_before(va, ia, vb, ib);
                if (swp) { sv[t] = vb; si[t] = ib; sv[ixj] = va; si[ixj] = ia; }
            }
            __syncthreads();
        }
    }

    int oidx = g * NN + (si[t] & 2047);
    if (t < K) { kept[oidx] = 1; scale[oidx] = sv[t]; }
    else       { kept[oidx] = 0; scale[oidx] = 0.f; }
    if (rankOut) rankOut[oidx] = t;
}

/* ---- readout v2: 1024 threads, 8 node-partitions x 128 cols, smem reduce ---- */
__global__ void __launch_bounds__(1024)
k_readout(const float* __restrict__ h, const int* __restrict__ kept,
          const float* __restrict__ scale, float* __restrict__ out,
          float invK, int accumulate) {
    __shared__ float ssc[NN];
    __shared__ int   skp[NN];
    __shared__ float rsum[8][128];
    __shared__ float rmax[8][128];

    int g = blockIdx.x, t = threadIdx.x;
    ssc[t] = scale[g * NN + t];
    skp[t] = kept[g * NN + t];
    __syncthreads();

    int sub = t >> 7;         /* 0..7 node partition */
    int j   = t & 127;        /* feature column */
    float sum = 0.f, mx = -INFINITY;
    int v0 = sub * 128;
#pragma unroll 4
    for (int v = v0; v < v0 + 128; v++) {
        if (skp[v]) {
            float hv = h[(g * NN + v) * NH + j] * ssc[v];
            sum += hv;
            mx = fmaxf(mx, hv);
        }
    }
    rsum[sub][j] = sum;
    rmax[sub][j] = mx;
    __syncthreads();

    if (t < 128) {
        float s = 0.f, m = -INFINITY;
#pragma unroll
        for (int i = 0; i < 8; i++) {
            s += rsum[i][t];
            m = fmaxf(m, rmax[i][t]);
        }
        float o0 = s * invK;
        if (accumulate) {
            out[g * 256 + t]       += o0;
            out[g * 256 + 128 + t] += m;
        } else {
            out[g * 256 + t]       = o0;
            out[g * 256 + 128 + t] = m;
        }
    }
}

/* ---------------- conv2 aggregation gather (fp32) ---------------- */
__global__ void __launch_bounds__(256)
k_gather2() {
    int tid  = threadIdx.x;
    int w    = tid >> 5;
    int lane = tid & 31;
    int v    = blockIdx.x * 8 + w;
    if (!g_kept1[v]) return;
    int rs = g_rows[v], re = g_rows[v + 1];
    int l4 = lane * 4;
    float4 a = make_float4(0.f, 0.f, 0.f, 0.f);
    for (int i = rs; i < re; i++) {
        int s = g_esrc[i];
        if (g_kept1[s]) {
            float sc = g_scale1[s];
            float4 hv = *(const float4*)&g_h1[s * NH + l4];
            a.x += hv.x * sc; a.y += hv.y * sc;
            a.z += hv.z * sc; a.w += hv.w * sc;
        }
    }
    *(float4*)&g_agg2[v * NH + l4] = a;
}

/* ---- conv2 GEMM v2 (128x128 tile, 8x8/thread) + fused logit2 epilogue:
       h2 = relu([agg2|h1*s1] @ [W2rel;W2root]^T + b2); logit2 = h2 . p2w ---- */
#define G2M 128
#define G2K 32
#define SST 132   /* smem row stride (floats): conflict-free, float4-aligned */
__global__ void __launch_bounds__(256)
k_gemm2(const float* __restrict__ W2rel, const float* __restrict__ b2,
        const float* __restrict__ W2root, const float* __restrict__ p2w) {
    __shared__ __align__(16) float As[G2K][SST];
    __shared__ __align__(16) float Ws[G2K][SST];
    __shared__ float sb2[NH];
    __shared__ float sp2[NH];
    __shared__ float slp[G2M][17];

    int tid = threadIdx.x;
    int m0  = blockIdx.x * G2M;
    if (tid < NH) { sb2[tid] = b2[tid]; sp2[tid] = p2w[tid]; }

    int tx = tid & 15;    /* col group: cols tx*8 .. tx*8+7 */
    int ty = tid >> 4;    /* row group: rows ty*8 .. ty*8+7 */

    float acc[8][8];
#pragma unroll
    for (int i = 0; i < 8; i++)
#pragma unroll
        for (int j = 0; j < 8; j++) acc[i][j] = 0.f;

    for (int kc = 0; kc < 2 * NH; kc += G2K) {
        /* stage A: 128 rows x 32 k, transposed into As[k][row] */
#pragma unroll
        for (int r = 0; r < 4; r++) {
            int id = tid + r * 256;
            int row = id >> 3;
            int k4  = id & 7;
            int kk  = kc + k4 * 4;
            int node = m0 + row;
            float4 val;
            if (kk < NH) {
                val = *(const float4*)&g_agg2[node * NH + kk];
            } else {
                float sc = g_kept1[node] ? g_scale1[node] : 0.f;
                float4 hh = *(const float4*)&g_h1[node * NH + (kk - NH)];
                val = make_float4(hh.x * sc, hh.y * sc, hh.z * sc, hh.w * sc);
            }
            int kl = k4 * 4;
            As[kl + 0][row] = val.x; As[kl + 1][row] = val.y;
            As[kl + 2][row] = val.z; As[kl + 3][row] = val.w;
        }
        /* stage W: 128 cols x 32 k into Ws[k][col] */
#pragma unroll
        for (int r = 0; r < 4; r++) {
            int id = tid + r * 256;
            int col = id >> 3;
            int k4  = id & 7;
            int kk  = kc + k4 * 4;
            const float* Wsrc = (kk < NH) ? W2rel : W2root;
            int kw = (kk < NH) ? kk : (kk - NH);
            float4 val = *(const float4*)&Wsrc[col * NH + kw];
            int kl = k4 * 4;
            Ws[kl + 0][col] = val.x; Ws[kl + 1][col] = val.y;
            Ws[kl + 2][col] = val.z; Ws[kl + 3][col] = val.w;
        }
        __syncthreads();
#pragma unroll
        for (int k = 0; k < G2K; k++) {
            float4 a0 = *(const float4*)&As[k][ty * 8];
            float4 a1 = *(const float4*)&As[k][ty * 8 + 4];
            float4 w0 = *(const float4*)&Ws[k][tx * 8];
            float4 w1 = *(const float4*)&Ws[k][tx * 8 + 4];
            float am[8] = {a0.x, a0.y, a0.z, a0.w, a1.x, a1.y, a1.z, a1.w};
            float wv[8] = {w0.x, w0.y, w0.z, w0.w, w1.x, w1.y, w1.z, w1.w};
#pragma unroll
            for (int mi = 0; mi < 8; mi++)
#pragma unroll
                for (int ji = 0; ji < 8; ji++)
                    acc[mi][ji] += am[mi] * wv[ji];
        }
        __syncthreads();
    }

    /* epilogue: bias + relu + store h2 + per-thread logit partial */
#pragma unroll
    for (int mi = 0; mi < 8; mi++) {
        int row  = ty * 8 + mi;
        int node = m0 + row;
        float o[8];
        float lp = 0.f;
#pragma unroll
        for (int ji = 0; ji < 8; ji++) {
            int c = tx * 8 + ji;
            float v = fmaxf(acc[mi][ji] + sb2[c], 0.f);
            o[ji] = v;
            lp += v * sp2[c];
        }
        *(float4*)&g_h2[node * NH + tx * 8]     = make_float4(o[0], o[1], o[2], o[3]);
        *(float4*)&g_h2[node * NH + tx * 8 + 4] = make_float4(o[4], o[5], o[6], o[7]);
        slp[row][tx] = lp;
    }
    __syncthreads();

    /* deterministic 16-way reduce -> logit2 */
    if (tid < G2M) {
        int node = m0 + tid;
        if (g_kept1[node]) {
            float s = 0.f;
#pragma unroll
            for (int i = 0; i < 16; i++) s += slp[tid][i];
            g_logit2[node] = s;
        }
    }
}

/* ---------------- launch ---------------- */
extern "C" void kernel_launch(void* const* d_in, const int* in_sizes, int n_in,
                              void* d_out, int out_size) {
    const float* x      = (const float*)d_in[0];
    const int*   ei     = (const int*)d_in[1];
    /* d_in[2] = batch (unused) */
    const float* W1rel  = (const float*)d_in[3];
    const float* b1     = (const float*)d_in[4];
    const float* W1root = (const float*)d_in[5];
    const float* p1w    = (const float*)d_in[6];
    const float* W2rel  = (const float*)d_in[7];
    const float* b2     = (const float*)d_in[8];
    const float* W2root = (const float*)d_in[9];
    const float* p2w    = (const float*)d_in[10];
    float* out = (float*)d_out;

    const int* src = ei;
    const int* dst = ei + NE;

    float* d_logit1;  cudaGetSymbolAddress((void**)&d_logit1, g_logit1);
    float* d_logit2;  cudaGetSymbolAddress((void**)&d_logit2, g_logit2);
    float* d_scale1;  cudaGetSymbolAddress((void**)&d_scale1, g_scale1);
    float* d_scale2;  cudaGetSymbolAddress((void**)&d_scale2, g_scale2);
    int*   d_kept1;   cudaGetSymbolAddress((void**)&d_kept1,  g_kept1);
    int*   d_kept2;   cudaGetSymbolAddress((void**)&d_kept2,  g_kept2);
    int*   d_rank1;   cudaGetSymbolAddress((void**)&d_rank1,  g_rank1);
    float* d_h1;      cudaGetSymbolAddress((void**)&d_h1,     g_h1);
    float* d_h2;      cudaGetSymbolAddress((void**)&d_h2,     g_h2);

    /* CSR build */
    k_zero_deg<<<NTOT / 256, 256>>>();
    k_hist<<<NE / 256, 256>>>(dst);
    k_scan<<<1, 1024>>>();
    k_scatter<<<NE / 256, 256>>>(src, dst);

    /* layer 1 */
    k_conv1<<<NTOT / 8, 256>>>(x, W1rel, b1, W1root, p1w);
    k_pool<<<NB, 1024>>>(d_logit1, (const int*)nullptr, (const int*)nullptr,
                         p1w, d_kept1, d_scale1, d_rank1, KP1);
    k_readout<<<NB, 1024>>>(d_h1, d_kept1, d_scale1, out, 1.0f / (float)KP1, 0);

    /* layer 2 (gemm2 fuses logit2) */
    k_gather2<<<NTOT / 8, 256>>>();
    k_gemm2<<<NTOT / G2M, 256>>>(W2rel, b2, W2root, p2w);
    k_pool<<<NB, 1024>>>(d_logit2, d_kept1, d_rank1,
                         p2w, d_kept2, d_scale2, (int*)nullptr, KP2);
    k_readout<<<NB, 1024>>>(d_h2, d_kept2, d_scale2, out, 1.0f / (float)KP2, 1);
}

// round 14
// speedup vs baseline: 1.8117x; 1.5696x over previous
#include <cuda_runtime.h>
#include <math.h>

#define NB   64
#define NN   1024
#define FIN  14
#define NH   128
#define NTOT (NB*NN)        /* 65536 */
#define NE   (NTOT*8)       /* 524288 */
#define KP1  820
#define KP2  656

/* ---------------- scratch (device globals; no allocs allowed) ---------------- */
__device__ __align__(16) int      g_deg[NTOT];
__device__ __align__(16) int      g_rows[NTOT + 16];
__device__ __align__(16) int      g_cur[NTOT];
__device__ int                    g_esrc[NE];
__device__ __align__(16) float    g_h1[NTOT * NH];
__device__ __align__(16) float    g_agg2[NTOT * NH];
__device__ __align__(16) float    g_h2[NTOT * NH];
__device__ float                  g_logit1[NTOT];
__device__ float                  g_logit2[NTOT];
__device__ float                  g_scale1[NTOT];
__device__ int                    g_kept1[NTOT];
__device__ int                    g_rank1[NTOT];

/* HW tanh: tanh.approx.f32 (MUFU.TANH) — matches the reference bit-for-bit. */
__device__ __forceinline__ float tanh_hw(float x) {
    float y;
    asm("tanh.approx.f32 %0, %1;" : "=f"(y) : "f"(x));
    return y;
}

/* ---------------- CSR build ---------------- */
__global__ void k_zero_deg() {
    int i = blockIdx.x * blockDim.x + threadIdx.x;
    if (i < NTOT) g_deg[i] = 0;
}

__global__ void k_hist(const int* __restrict__ dst) {
    int e = blockIdx.x * blockDim.x + threadIdx.x;
    if (e < NE) atomicAdd(&g_deg[dst[e]], 1);
}

/* single-block exclusive scan of 65536 ints, int4-vectorized */
__global__ void __launch_bounds__(1024) k_scan() {
    __shared__ int ssum[1024];
    int t = threadIdx.x;
    int base = t * 64;
    const int4* dv = (const int4*)&g_deg[base];
    int s = 0;
#pragma unroll
    for (int q = 0; q < 16; q++) {
        int4 d = dv[q];
        s += d.x + d.y + d.z + d.w;
    }
    ssum[t] = s;
    __syncthreads();
    for (int off = 1; off < 1024; off <<= 1) {
        int v = 0;
        if (t >= off) v = ssum[t - off];
        __syncthreads();
        if (t >= off) ssum[t] += v;
        __syncthreads();
    }
    int run = ssum[t] - s;
    int4* rv = (int4*)&g_rows[base];
    int4* cv = (int4*)&g_cur[base];
#pragma unroll
    for (int q = 0; q < 16; q++) {
        int4 d = dv[q];
        int4 r;
        r.x = run; run += d.x;
        r.y = run; run += d.y;
        r.z = run; run += d.z;
        r.w = run; run += d.w;
        rv[q] = r;
        cv[q] = r;
    }
    if (t == 1023) g_rows[NTOT] = run;
}

__global__ void k_scatter(const int* __restrict__ src, const int* __restrict__ dst) {
    int e = blockIdx.x * blockDim.x + threadIdx.x;
    if (e < NE) {
        int p = atomicAdd(&g_cur[dst[e]], 1);
        g_esrc[p] = src[e];
    }
}

/* ---- conv1: grid-stride, warp per node, MLP-2 gather, pure fp32 ---- */
#define C1GRID 1184
__global__ void __launch_bounds__(256)
k_conv1(const float* __restrict__ x,
        const float* __restrict__ W1rel, const float* __restrict__ b1,
        const float* __restrict__ W1root, const float* __restrict__ p1w) {
    __shared__ float sWrel[NH * FIN];
    __shared__ float sWroot[NH * FIN];
    __shared__ float sb[NH];
    __shared__ float spw[NH];
    __shared__ float sAgg[8][FIN];
    __shared__ float sXv[8][FIN];

    int tid = threadIdx.x;
    for (int i = tid; i < NH * FIN; i += 256) {
        sWrel[i]  = W1rel[i];
        sWroot[i] = W1root[i];
    }
    if (tid < NH) { sb[tid] = b1[tid]; spw[tid] = p1w[tid]; }
    __syncthreads();

    int w    = tid >> 5;
    int lane = tid & 31;

    for (int blk = blockIdx.x; blk < NTOT / 8; blk += C1GRID) {
        int v = blk * 8 + w;
        int rs = g_rows[v], re = g_rows[v + 1];
        if (lane < FIN) {
            float a0 = 0.f, a1 = 0.f;
            int i = rs;
            for (; i + 1 < re; i += 2) {
                int s0 = g_esrc[i];
                int s1 = g_esrc[i + 1];
                a0 += x[s0 * FIN + lane];
                a1 += x[s1 * FIN + lane];
            }
            if (i < re) a0 += x[g_esrc[i] * FIN + lane];
            sAgg[w][lane] = a0 + a1;
            sXv[w][lane]  = x[v * FIN + lane];
        }
        __syncwarp();

        float lp = 0.f;
        float hj[4];
#pragma unroll
        for (int jj = 0; jj < 4; jj++) {
            int j = lane * 4 + jj;
            float acc = sb[j];
#pragma unroll
            for (int k = 0; k < FIN; k++)
                acc += sAgg[w][k] * sWrel[j * FIN + k] + sXv[w][k] * sWroot[j * FIN + k];
            acc = fmaxf(acc, 0.f);
            hj[jj] = acc;
            lp += acc * spw[j];
        }
        *(float4*)&g_h1[v * NH + lane * 4] = make_float4(hj[0], hj[1], hj[2], hj[3]);
#pragma unroll
        for (int o = 16; o > 0; o >>= 1) lp += __shfl_xor_sync(0xffffffffu, lp, o);
        if (lane == 0) g_logit1[v] = lp;
        __syncwarp();
    }
}

/* ------- per-graph top-K (tanh.approx score DESC, tie-key ASC) + FUSED readout.
   Pool semantics identical to R12/R13; readout runs in the same block using
   the freshly computed kept/scale from smem. ------- */
__device__ __forceinline__ bool pair_before(float va, int ia, float vb, int ib) {
    return (va > vb) || (va == vb && ia < ib);
}

__global__ void __launch_bounds__(1024)
k_pool_readout(const float* __restrict__ logitArr, const int* __restrict__ valid,
               const int* __restrict__ keyIn, const float* __restrict__ w,
               int* __restrict__ keptOut, float* __restrict__ scaleOut,
               int* __restrict__ rankOut,
               const float* __restrict__ h, float* __restrict__ out,
               float invK, int accumulate, int K) {
    __shared__ float sv[NN];
    __shared__ int   si[NN];
    __shared__ float red[128];
    __shared__ float snorm;
    __shared__ float ksc[NN];
    __shared__ int   kkp[NN];
    __shared__ float rsum[8][128];
    __shared__ float rmax[8][128];

    int t = threadIdx.x, g = blockIdx.x;

    /* fp32 ||w|| */
    if (t < 128) { float w0 = w[t]; red[t] = w0 * w0; }
    __syncthreads();
    if (t < 64) red[t] += red[t + 64];
    __syncthreads();
    if (t < 32) {
        float s = red[t] + red[t + 32];
#pragma unroll
        for (int o = 16; o > 0; o >>= 1) s += __shfl_xor_sync(0xffffffffu, s, o);
        if (t == 0) snorm = __fsqrt_rn(s);
    }
    __syncthreads();

    int orig = g * NN + t;
    float scv = -3.0f;
    int   key;
    if (valid == nullptr || valid[orig]) {
        scv = tanh_hw(__fdiv_rn(logitArr[orig], snorm));
        key = keyIn ? keyIn[orig] : t;
    } else {
        key = 500000 + t;
    }
    sv[t] = scv;
    si[t] = key * 2048 + t;
    __syncthreads();

    for (int k = 2; k <= NN; k <<= 1) {
        for (int j = k >> 1; j > 0; j >>= 1) {
            int ixj = t ^ j;
            if (ixj > t) {
                float va = sv[t], vb = sv[ixj];
                int   ia = si[t], ib = si[ixj];
                bool up = ((t & k) == 0);
                bool swp = up ? pair_before(vb, ib, va, ia)
                              : pair_before(va, ia, vb, ib);
                if (swp) { sv[t] = vb; si[t] = ib; sv[ixj] = va; si[ixj] = ia; }
            }
            __syncthreads();
        }
    }

    int slot = si[t] & 2047;
    int kp   = (t < K) ? 1 : 0;
    float sc = kp ? sv[t] : 0.f;
    kkp[slot] = kp;
    ksc[slot] = sc;
    if (keptOut)  keptOut[g * NN + slot]  = kp;
    if (scaleOut) scaleOut[g * NN + slot] = sc;
    if (rankOut)  rankOut[g * NN + slot]  = t;
    __syncthreads();

    /* fused readout: 8 node-partitions x 128 cols */
    int sub = t >> 7;
    int j   = t & 127;
    float sum = 0.f, mx = -INFINITY;
    int v0 = sub * 128;
#pragma unroll 4
    for (int v = v0; v < v0 + 128; v++) {
        if (kkp[v]) {
            float hv = h[(g * NN + v) * NH + j] * ksc[v];
            sum += hv;
            mx = fmaxf(mx, hv);
        }
    }
    rsum[sub][j] = sum;
    rmax[sub][j] = mx;
    __syncthreads();

    if (t < 128) {
        float s = 0.f, m = -INFINITY;
#pragma unroll
        for (int i = 0; i < 8; i++) {
            s += rsum[i][t];
            m = fmaxf(m, rmax[i][t]);
        }
        float o0 = s * invK;
        if (accumulate) {
            out[g * 256 + t]       += o0;
            out[g * 256 + 128 + t] += m;
        } else {
            out[g * 256 + t]       = o0;
            out[g * 256 + 128 + t] = m;
        }
    }
}

/* ---------------- conv2 aggregation gather, MLP-2 (fp32) ---------------- */
__global__ void __launch_bounds__(256)
k_gather2() {
    int tid  = threadIdx.x;
    int w    = tid >> 5;
    int lane = tid & 31;
    int v    = blockIdx.x * 8 + w;
    if (!g_kept1[v]) return;
    int rs = g_rows[v], re = g_rows[v + 1];
    int l4 = lane * 4;
    float4 a0 = make_float4(0.f, 0.f, 0.f, 0.f);
    float4 a1 = make_float4(0.f, 0.f, 0.f, 0.f);
    int i = rs;
    for (; i + 1 < re; i += 2) {
        int s0 = g_esrc[i];
        int s1 = g_esrc[i + 1];
        float c0 = g_scale1[s0];
        float c1 = g_scale1[s1];
        if (c0 != 0.f) {
            float4 hv = *(const float4*)&g_h1[s0 * NH + l4];
            a0.x += hv.x * c0; a0.y += hv.y * c0;
            a0.z += hv.z * c0; a0.w += hv.w * c0;
        }
        if (c1 != 0.f) {
            float4 hv = *(const float4*)&g_h1[s1 * NH + l4];
            a1.x += hv.x * c1; a1.y += hv.y * c1;
            a1.z += hv.z * c1; a1.w += hv.w * c1;
        }
    }
    if (i < re) {
        int s0 = g_esrc[i];
        float c0 = g_scale1[s0];
        if (c0 != 0.f) {
            float4 hv = *(const float4*)&g_h1[s0 * NH + l4];
            a0.x += hv.x * c0; a0.y += hv.y * c0;
            a0.z += hv.z * c0; a0.w += hv.w * c0;
        }
    }
    a0.x += a1.x; a0.y += a1.y; a0.z += a1.z; a0.w += a1.w;
    *(float4*)&g_agg2[v * NH + l4] = a0;
}

/* ---- conv2 GEMM (128x128 tile, 8x8/thread) + fused logit2 epilogue ---- */
#define G2M 128
#define G2K 32
#define SST 132
__global__ void __launch_bounds__(256, 2)
k_gemm2(const float* __restrict__ W2rel, const float* __restrict__ b2,
        const float* __restrict__ W2root, const float* __restrict__ p2w) {
    __shared__ __align__(16) float As[G2K][SST];
    __shared__ __align__(16) float Ws[G2K][SST];
    __shared__ float sb2[NH];
    __shared__ float sp2[NH];
    __shared__ float slp[G2M][17];

    int tid = threadIdx.x;
    int m0  = blockIdx.x * G2M;
    if (tid < NH) { sb2[tid] = b2[tid]; sp2[tid] = p2w[tid]; }

    int tx = tid & 15;
    int ty = tid >> 4;

    float acc[8][8];
#pragma unroll
    for (int i = 0; i < 8; i++)
#pragma unroll
        for (int j = 0; j < 8; j++) acc[i][j] = 0.f;

    for (int kc = 0; kc < 2 * NH; kc += G2K) {
#pragma unroll
        for (int r = 0; r < 4; r++) {
            int id = tid + r * 256;
            int row = id >> 3;
            int k4  = id & 7;
            int kk  = kc + k4 * 4;
            int node = m0 + row;
            float4 val;
            if (kk < NH) {
                val = *(const float4*)&g_agg2[node * NH + kk];
            } else {
                float sc = g_kept1[node] ? g_scale1[node] : 0.f;
                float4 hh = *(const float4*)&g_h1[node * NH + (kk - NH)];
                val = make_float4(hh.x * sc, hh.y * sc, hh.z * sc, hh.w * sc);
            }
            int kl = k4 * 4;
            As[kl + 0][row] = val.x; As[kl + 1][row] = val.y;
            As[kl + 2][row] = val.z; As[kl + 3][row] = val.w;
        }
#pragma unroll
        for (int r = 0; r < 4; r++) {
            int id = tid + r * 256;
            int col = id >> 3;
            int k4  = id & 7;
            int kk  = kc + k4 * 4;
            const float* Wsrc = (kk < NH) ? W2rel : W2root;
            int kw = (kk < NH) ? kk : (kk - NH);
            float4 val = *(const float4*)&Wsrc[col * NH + kw];
            int kl = k4 * 4;
            Ws[kl + 0][col] = val.x; Ws[kl + 1][col] = val.y;
            Ws[kl + 2][col] = val.z; Ws[kl + 3][col] = val.w;
        }
        __syncthreads();
#pragma unroll
        for (int k = 0; k < G2K; k++) {
            float4 a0 = *(const float4*)&As[k][ty * 8];
            float4 a1 = *(const float4*)&As[k][ty * 8 + 4];
            float4 w0 = *(const float4*)&Ws[k][tx * 8];
            float4 w1 = *(const float4*)&Ws[k][tx * 8 + 4];
            float am[8] = {a0.x, a0.y, a0.z, a0.w, a1.x, a1.y, a1.z, a1.w};
            float wv[8] = {w0.x, w0.y, w0.z, w0.w, w1.x, w1.y, w1.z, w1.w};
#pragma unroll
            for (int mi = 0; mi < 8; mi++)
#pragma unroll
                for (int ji = 0; ji < 8; ji++)
                    acc[mi][ji] += am[mi] * wv[ji];
        }
        __syncthreads();
    }

#pragma unroll
    for (int mi = 0; mi < 8; mi++) {
        int row  = ty * 8 + mi;
        int node = m0 + row;
        float o[8];
        float lp = 0.f;
#pragma unroll
        for (int ji = 0; ji < 8; ji++) {
            int c = tx * 8 + ji;
            float v = fmaxf(acc[mi][ji] + sb2[c], 0.f);
            o[ji] = v;
            lp += v * sp2[c];
        }
        *(float4*)&g_h2[node * NH + tx * 8]     = make_float4(o[0], o[1], o[2], o[3]);
        *(float4*)&g_h2[node * NH + tx * 8 + 4] = make_float4(o[4], o[5], o[6], o[7]);
        slp[row][tx] = lp;
    }
    __syncthreads();

    if (tid < G2M) {
        int node = m0 + tid;
        if (g_kept1[node]) {
            float s = 0.f;
#pragma unroll
            for (int i = 0; i < 16; i++) s += slp[tid][i];
            g_logit2[node] = s;
        }
    }
}

/* ---------------- launch ---------------- */
extern "C" void kernel_launch(void* const* d_in, const int* in_sizes, int n_in,
                              void* d_out, int out_size) {
    const float* x      = (const float*)d_in[0];
    const int*   ei     = (const int*)d_in[1];
    /* d_in[2] = batch (unused) */
    const float* W1rel  = (const float*)d_in[3];
    const float* b1     = (const float*)d_in[4];
    const float* W1root = (const float*)d_in[5];
    const float* p1w    = (const float*)d_in[6];
    const float* W2rel  = (const float*)d_in[7];
    const float* b2     = (const float*)d_in[8];
    const float* W2root = (const float*)d_in[9];
    const float* p2w    = (const float*)d_in[10];
    float* out = (float*)d_out;

    const int* src = ei;
    const int* dst = ei + NE;

    float* d_logit1;  cudaGetSymbolAddress((void**)&d_logit1, g_logit1);
    float* d_logit2;  cudaGetSymbolAddress((void**)&d_logit2, g_logit2);
    float* d_scale1;  cudaGetSymbolAddress((void**)&d_scale1, g_scale1);
    int*   d_kept1;   cudaGetSymbolAddress((void**)&d_kept1,  g_kept1);
    int*   d_rank1;   cudaGetSymbolAddress((void**)&d_rank1,  g_rank1);
    float* d_h1;      cudaGetSymbolAddress((void**)&d_h1,     g_h1);
    float* d_h2;      cudaGetSymbolAddress((void**)&d_h2,     g_h2);

    /* CSR build */
    k_zero_deg<<<NTOT / 256, 256>>>();
    k_hist<<<NE / 256, 256>>>(dst);
    k_scan<<<1, 1024>>>();
    k_scatter<<<NE / 256, 256>>>(src, dst);

    /* layer 1: conv + (pool ⊕ readout) */
    k_conv1<<<C1GRID, 256>>>(x, W1rel, b1, W1root, p1w);
    k_pool_readout<<<NB, 1024>>>(d_logit1, (const int*)nullptr, (const int*)nullptr,
                                 p1w, d_kept1, d_scale1, d_rank1,
                                 d_h1, out, 1.0f / (float)KP1, 0, KP1);

    /* layer 2: gather + (gemm ⊕ logit2) + (pool ⊕ readout) */
    k_gather2<<<NTOT / 8, 256>>>();
    k_gemm2<<<NTOT / G2M, 256>>>(W2rel, b2, W2root, p2w);
    k_pool_readout<<<NB, 1024>>>(d_logit2, d_kept1, d_rank1,
                                 p2w, (int*)nullptr, (float*)nullptr, (int*)nullptr,
                                 d_h2, out, 1.0f / (float)KP2, 1, KP2);
}

// round 15
// speedup vs baseline: 2.2418x; 1.2374x over previous
#include <cuda_runtime.h>
#include <math.h>

#define NB   64
#define NN   1024
#define FIN  14
#define NH   128
#define NTOT (NB*NN)        /* 65536 */
#define NE   (NTOT*8)       /* 524288 */
#define KP1  820
#define KP2  656

/* ---------------- scratch (device globals; no allocs allowed) ---------------- */
__device__ __align__(16) int      g_deg[NTOT];
__device__ __align__(16) int      g_rows[NTOT + 16];
__device__ __align__(16) int      g_cur[NTOT];
__device__ int                    g_esrc[NE];
__device__ __align__(16) float    g_h1[NTOT * NH];
__device__ __align__(16) float    g_agg2[NTOT * NH];
__device__ __align__(16) float    g_h2[NTOT * NH];
__device__ float                  g_logit1[NTOT];
__device__ float                  g_logit2[NTOT];
__device__ float                  g_scale1[NTOT];
__device__ int                    g_kept1[NTOT];
__device__ int                    g_rank1[NTOT];

/* HW tanh: tanh.approx.f32 (MUFU.TANH) — matches the reference bit-for-bit. */
__device__ __forceinline__ float tanh_hw(float x) {
    float y;
    asm("tanh.approx.f32 %0, %1;" : "=f"(y) : "f"(x));
    return y;
}

/* TF32 operand rounding (RNA) — cuBLAS convention for f32 tensor-core GEMM */
__device__ __forceinline__ unsigned tf32u(float a) {
    unsigned r;
    asm("cvt.rna.tf32.f32 %0, %1;" : "=r"(r) : "f"(a));
    return r;
}

/* ---------------- CSR build ---------------- */
__global__ void k_zero_deg() {
    int i = blockIdx.x * blockDim.x + threadIdx.x;
    if (i < NTOT) g_deg[i] = 0;
}

__global__ void k_hist(const int* __restrict__ dst) {
    int e = blockIdx.x * blockDim.x + threadIdx.x;
    if (e < NE) atomicAdd(&g_deg[dst[e]], 1);
}

__global__ void __launch_bounds__(1024) k_scan() {
    __shared__ int ssum[1024];
    int t = threadIdx.x;
    int base = t * 64;
    const int4* dv = (const int4*)&g_deg[base];
    int s = 0;
#pragma unroll
    for (int q = 0; q < 16; q++) {
        int4 d = dv[q];
        s += d.x + d.y + d.z + d.w;
    }
    ssum[t] = s;
    __syncthreads();
    for (int off = 1; off < 1024; off <<= 1) {
        int v = 0;
        if (t >= off) v = ssum[t - off];
        __syncthreads();
        if (t >= off) ssum[t] += v;
        __syncthreads();
    }
    int run = ssum[t] - s;
    int4* rv = (int4*)&g_rows[base];
    int4* cv = (int4*)&g_cur[base];
#pragma unroll
    for (int q = 0; q < 16; q++) {
        int4 d = dv[q];
        int4 r;
        r.x = run; run += d.x;
        r.y = run; run += d.y;
        r.z = run; run += d.z;
        r.w = run; run += d.w;
        rv[q] = r;
        cv[q] = r;
    }
    if (t == 1023) g_rows[NTOT] = run;
}

__global__ void k_scatter(const int* __restrict__ src, const int* __restrict__ dst) {
    int e = blockIdx.x * blockDim.x + threadIdx.x;
    if (e < NE) {
        int p = atomicAdd(&g_cur[dst[e]], 1);
        g_esrc[p] = src[e];
    }
}

/* ---- conv1: grid-stride, warp per node, MLP-2 gather, pure fp32 ---- */
#define C1GRID 1184
__global__ void __launch_bounds__(256)
k_conv1(const float* __restrict__ x,
        const float* __restrict__ W1rel, const float* __restrict__ b1,
        const float* __restrict__ W1root, const float* __restrict__ p1w) {
    __shared__ float sWrel[NH * FIN];
    __shared__ float sWroot[NH * FIN];
    __shared__ float sb[NH];
    __shared__ float spw[NH];
    __shared__ float sAgg[8][FIN];
    __shared__ float sXv[8][FIN];

    int tid = threadIdx.x;
    for (int i = tid; i < NH * FIN; i += 256) {
        sWrel[i]  = W1rel[i];
        sWroot[i] = W1root[i];
    }
    if (tid < NH) { sb[tid] = b1[tid]; spw[tid] = p1w[tid]; }
    __syncthreads();

    int w    = tid >> 5;
    int lane = tid & 31;

    for (int blk = blockIdx.x; blk < NTOT / 8; blk += C1GRID) {
        int v = blk * 8 + w;
        int rs = g_rows[v], re = g_rows[v + 1];
        if (lane < FIN) {
            float a0 = 0.f, a1 = 0.f;
            int i = rs;
            for (; i + 1 < re; i += 2) {
                int s0 = g_esrc[i];
                int s1 = g_esrc[i + 1];
                a0 += x[s0 * FIN + lane];
                a1 += x[s1 * FIN + lane];
            }
            if (i < re) a0 += x[g_esrc[i] * FIN + lane];
            sAgg[w][lane] = a0 + a1;
            sXv[w][lane]  = x[v * FIN + lane];
        }
        __syncwarp();

        float lp = 0.f;
        float hj[4];
#pragma unroll
        for (int jj = 0; jj < 4; jj++) {
            int j = lane * 4 + jj;
            float acc = sb[j];
#pragma unroll
            for (int k = 0; k < FIN; k++)
                acc += sAgg[w][k] * sWrel[j * FIN + k] + sXv[w][k] * sWroot[j * FIN + k];
            acc = fmaxf(acc, 0.f);
            hj[jj] = acc;
            lp += acc * spw[j];
        }
        *(float4*)&g_h1[v * NH + lane * 4] = make_float4(hj[0], hj[1], hj[2], hj[3]);
#pragma unroll
        for (int o = 16; o > 0; o >>= 1) lp += __shfl_xor_sync(0xffffffffu, lp, o);
        if (lane == 0) g_logit1[v] = lp;
        __syncwarp();
    }
}

/* ------- per-graph top-K + FUSED readout (semantics from R12) ------- */
__device__ __forceinline__ bool pair_before(float va, int ia, float vb, int ib) {
    return (va > vb) || (va == vb && ia < ib);
}

__global__ void __launch_bounds__(1024)
k_pool_readout(const float* __restrict__ logitArr, const int* __restrict__ valid,
               const int* __restrict__ keyIn, const float* __restrict__ w,
               int* __restrict__ keptOut, float* __restrict__ scaleOut,
               int* __restrict__ rankOut,
               const float* __restrict__ h, float* __restrict__ out,
               float invK, int accumulate, int K) {
    __shared__ float sv[NN];
    __shared__ int   si[NN];
    __shared__ float red[128];
    __shared__ float snorm;
    __shared__ float ksc[NN];
    __shared__ int   kkp[NN];
    __shared__ float rsum[8][128];
    __shared__ float rmax[8][128];

    int t = threadIdx.x, g = blockIdx.x;

    if (t < 128) { float w0 = w[t]; red[t] = w0 * w0; }
    __syncthreads();
    if (t < 64) red[t] += red[t + 64];
    __syncthreads();
    if (t < 32) {
        float s = red[t] + red[t + 32];
#pragma unroll
        for (int o = 16; o > 0; o >>= 1) s += __shfl_xor_sync(0xffffffffu, s, o);
        if (t == 0) snorm = __fsqrt_rn(s);
    }
    __syncthreads();

    int orig = g * NN + t;
    float scv = -3.0f;
    int   key;
    if (valid == nullptr || valid[orig]) {
        scv = tanh_hw(__fdiv_rn(logitArr[orig], snorm));
        key = keyIn ? keyIn[orig] : t;
    } else {
        key = 500000 + t;
    }
    sv[t] = scv;
    si[t] = key * 2048 + t;
    __syncthreads();

    for (int k = 2; k <= NN; k <<= 1) {
        for (int j = k >> 1; j > 0; j >>= 1) {
            int ixj = t ^ j;
            if (ixj > t) {
                float va = sv[t], vb = sv[ixj];
                int   ia = si[t], ib = si[ixj];
                bool up = ((t & k) == 0);
                bool swp = up ? pair_before(vb, ib, va, ia)
                              : pair_before(va, ia, vb, ib);
                if (swp) { sv[t] = vb; si[t] = ib; sv[ixj] = va; si[ixj] = ia; }
            }
            __syncthreads();
        }
    }

    int slot = si[t] & 2047;
    int kp   = (t < K) ? 1 : 0;
    float sc = kp ? sv[t] : 0.f;
    kkp[slot] = kp;
    ksc[slot] = sc;
    if (keptOut)  keptOut[g * NN + slot]  = kp;
    if (scaleOut) scaleOut[g * NN + slot] = sc;
    if (rankOut)  rankOut[g * NN + slot]  = t;
    __syncthreads();

    int sub = t >> 7;
    int j   = t & 127;
    float sum = 0.f, mx = -INFINITY;
    int v0 = sub * 128;
#pragma unroll 4
    for (int v = v0; v < v0 + 128; v++) {
        if (kkp[v]) {
            float hv = h[(g * NN + v) * NH + j] * ksc[v];
            sum += hv;
            mx = fmaxf(mx, hv);
        }
    }
    rsum[sub][j] = sum;
    rmax[sub][j] = mx;
    __syncthreads();

    if (t < 128) {
        float s = 0.f, m = -INFINITY;
#pragma unroll
        for (int i = 0; i < 8; i++) {
            s += rsum[i][t];
            m = fmaxf(m, rmax[i][t]);
        }
        float o0 = s * invK;
        if (accumulate) {
            out[g * 256 + t]       += o0;
            out[g * 256 + 128 + t] += m;
        } else {
            out[g * 256 + t]       = o0;
            out[g * 256 + 128 + t] = m;
        }
    }
}

/* ---------------- conv2 aggregation gather, MLP-2 (fp32) ---------------- */
__global__ void __launch_bounds__(256)
k_gather2() {
    int tid  = threadIdx.x;
    int w    = tid >> 5;
    int lane = tid & 31;
    int v    = blockIdx.x * 8 + w;
    if (!g_kept1[v]) return;
    int rs = g_rows[v], re = g_rows[v + 1];
    int l4 = lane * 4;
    float4 a0 = make_float4(0.f, 0.f, 0.f, 0.f);
    float4 a1 = make_float4(0.f, 0.f, 0.f, 0.f);
    int i = rs;
    for (; i + 1 < re; i += 2) {
        int s0 = g_esrc[i];
        int s1 = g_esrc[i + 1];
        float c0 = g_scale1[s0];
        float c1 = g_scale1[s1];
        if (c0 != 0.f) {
            float4 hv = *(const float4*)&g_h1[s0 * NH + l4];
            a0.x += hv.x * c0; a0.y += hv.y * c0;
            a0.z += hv.z * c0; a0.w += hv.w * c0;
        }
        if (c1 != 0.f) {
            float4 hv = *(const float4*)&g_h1[s1 * NH + l4];
            a1.x += hv.x * c1; a1.y += hv.y * c1;
            a1.z += hv.z * c1; a1.w += hv.w * c1;
        }
    }
    if (i < re) {
        int s0 = g_esrc[i];
        float c0 = g_scale1[s0];
        if (c0 != 0.f) {
            float4 hv = *(const float4*)&g_h1[s0 * NH + l4];
            a0.x += hv.x * c0; a0.y += hv.y * c0;
            a0.z += hv.z * c0; a0.w += hv.w * c0;
        }
    }
    a0.x += a1.x; a0.y += a1.y; a0.z += a1.z; a0.w += a1.w;
    *(float4*)&g_agg2[v * NH + l4] = a0;
}

/* ---- conv2 GEMM v3: TF32 tensor cores (mma.m16n8k8) + fused logit2.
       Block 128x128, K=256 in 8 chunks of 32. 8 warps: 4 along M x 2 along N;
       warp tile 32x64 = 2 m-tiles x 8 n-tiles. Smem [row][k] stride 36 ->
       conflict-free fragment loads (bank = 4g+tg). ---- */
#define G2M  128
#define G2K  32
#define KSTR 36
__global__ void __launch_bounds__(256, 2)
k_gemm2(const float* __restrict__ W2rel, const float* __restrict__ b2,
        const float* __restrict__ W2root, const float* __restrict__ p2w) {
    __shared__ __align__(16) unsigned As[G2M * KSTR];
    __shared__ __align__(16) unsigned Ws[G2M * KSTR];
    __shared__ float sb2[NH];
    __shared__ float sp2[NH];
    __shared__ float slp[G2M][2];

    int tid  = threadIdx.x;
    int m0   = blockIdx.x * G2M;
    int warp = tid >> 5;
    int lane = tid & 31;
    int gq   = lane >> 2;   /* group id 0..7 */
    int tg   = lane & 3;    /* thread-in-group */
    int wm   = warp >> 1;   /* 0..3: 32-row band */
    int wn   = warp & 1;    /* 0..1: 64-col half */
    int rbw  = wm * 32;
    int cbw  = wn * 64;

    if (tid < NH) { sb2[tid] = b2[tid]; sp2[tid] = p2w[tid]; }

    float d[2][8][4];
#pragma unroll
    for (int mt = 0; mt < 2; mt++)
#pragma unroll
        for (int nt = 0; nt < 8; nt++)
#pragma unroll
            for (int q = 0; q < 4; q++) d[mt][nt][q] = 0.f;

    for (int kc = 0; kc < 2 * NH; kc += G2K) {
        /* stage A rows: 128 x 32, [row][k], tf32-rounded */
#pragma unroll
        for (int r = 0; r < 4; r++) {
            int id  = tid + r * 256;
            int row = id >> 3;
            int k4  = id & 7;
            int kk  = kc + k4 * 4;
            int node = m0 + row;
            float4 val;
            if (kk < NH) {
                val = *(const float4*)&g_agg2[node * NH + kk];
            } else {
                float sc = g_kept1[node] ? g_scale1[node] : 0.f;
                float4 hh = *(const float4*)&g_h1[node * NH + (kk - NH)];
                val = make_float4(hh.x * sc, hh.y * sc, hh.z * sc, hh.w * sc);
            }
            unsigned* p = &As[row * KSTR + k4 * 4];
            p[0] = tf32u(val.x); p[1] = tf32u(val.y);
            p[2] = tf32u(val.z); p[3] = tf32u(val.w);
        }
        /* stage W cols: 128 x 32, [col][k], tf32-rounded */
#pragma unroll
        for (int r = 0; r < 4; r++) {
            int id  = tid + r * 256;
            int col = id >> 3;
            int k4  = id & 7;
            int kk  = kc + k4 * 4;
            const float* Wsrc = (kk < NH) ? W2rel : W2root;
            int kw = (kk < NH) ? kk : (kk - NH);
            float4 val = *(const float4*)&Wsrc[col * NH + kw];
            unsigned* p = &Ws[col * KSTR + k4 * 4];
            p[0] = tf32u(val.x); p[1] = tf32u(val.y);
            p[2] = tf32u(val.z); p[3] = tf32u(val.w);
        }
        __syncthreads();

#pragma unroll
        for (int ks = 0; ks < 4; ks++) {
            int kb = ks * 8;
            unsigned b0[8], b1[8];
#pragma unroll
            for (int nt = 0; nt < 8; nt++) {
                int cb = cbw + nt * 8;
                b0[nt] = Ws[(cb + gq) * KSTR + kb + tg];
                b1[nt] = Ws[(cb + gq) * KSTR + kb + tg + 4];
            }
#pragma unroll
            for (int mt = 0; mt < 2; mt++) {
                int rb = rbw + mt * 16;
                unsigned a0 = As[(rb + gq) * KSTR + kb + tg];
                unsigned a1 = As[(rb + gq + 8) * KSTR + kb + tg];
                unsigned a2 = As[(rb + gq) * KSTR + kb + tg + 4];
                unsigned a3 = As[(rb + gq + 8) * KSTR + kb + tg + 4];
#pragma unroll
                for (int nt = 0; nt < 8; nt++) {
                    asm volatile(
                        "mma.sync.aligned.m16n8k8.row.col.f32.tf32.tf32.f32 "
                        "{%0,%1,%2,%3}, {%4,%5,%6,%7}, {%8,%9}, {%0,%1,%2,%3};"
                        : "+f"(d[mt][nt][0]), "+f"(d[mt][nt][1]),
                          "+f"(d[mt][nt][2]), "+f"(d[mt][nt][3])
                        : "r"(a0), "r"(a1), "r"(a2), "r"(a3),
                          "r"(b0[nt]), "r"(b1[nt]));
                }
            }
        }
        __syncthreads();
    }

    /* epilogue: bias + relu + h2 store + logit2 partials */
#pragma unroll
    for (int mt = 0; mt < 2; mt++) {
        int r0 = rbw + mt * 16 + gq;
        int r1 = r0 + 8;
        float lp0 = 0.f, lp1 = 0.f;
#pragma unroll
        for (int nt = 0; nt < 8; nt++) {
            int c0 = cbw + nt * 8 + 2 * tg;
            int c1 = c0 + 1;
            float v00 = fmaxf(d[mt][nt][0] + sb2[c0], 0.f);
            float v01 = fmaxf(d[mt][nt][1] + sb2[c1], 0.f);
            float v10 = fmaxf(d[mt][nt][2] + sb2[c0], 0.f);
            float v11 = fmaxf(d[mt][nt][3] + sb2[c1], 0.f);
            *(float2*)&g_h2[(m0 + r0) * NH + c0] = make_float2(v00, v01);
            *(float2*)&g_h2[(m0 + r1) * NH + c0] = make_float2(v10, v11);
            lp0 += v00 * sp2[c0] + v01 * sp2[c1];
            lp1 += v10 * sp2[c0] + v11 * sp2[c1];
        }
        lp0 += __shfl_xor_sync(0xffffffffu, lp0, 1);
        lp0 += __shfl_xor_sync(0xffffffffu, lp0, 2);
        lp1 += __shfl_xor_sync(0xffffffffu, lp1, 1);
        lp1 += __shfl_xor_sync(0xffffffffu, lp1, 2);
        if (tg == 0) {
            slp[r0][wn] = lp0;
            slp[r1][wn] = lp1;
        }
    }
    __syncthreads();

    if (tid < G2M) {
        int node = m0 + tid;
        if (g_kept1[node]) g_logit2[node] = slp[tid][0] + slp[tid][1];
    }
}

/* ---------------- launch ---------------- */
extern "C" void kernel_launch(void* const* d_in, const int* in_sizes, int n_in,
                              void* d_out, int out_size) {
    const float* x      = (const float*)d_in[0];
    const int*   ei     = (const int*)d_in[1];
    /* d_in[2] = batch (unused) */
    const float* W1rel  = (const float*)d_in[3];
    const float* b1     = (const float*)d_in[4];
    const float* W1root = (const float*)d_in[5];
    const float* p1w    = (const float*)d_in[6];
    const float* W2rel  = (const float*)d_in[7];
    const float* b2     = (const float*)d_in[8];
    const float* W2root = (const float*)d_in[9];
    const float* p2w    = (const float*)d_in[10];
    float* out = (float*)d_out;

    const int* src = ei;
    const int* dst = ei + NE;

    float* d_logit1;  cudaGetSymbolAddress((void**)&d_logit1, g_logit1);
    float* d_logit2;  cudaGetSymbolAddress((void**)&d_logit2, g_logit2);
    float* d_scale1;  cudaGetSymbolAddress((void**)&d_scale1, g_scale1);
    int*   d_kept1;   cudaGetSymbolAddress((void**)&d_kept1,  g_kept1);
    int*   d_rank1;   cudaGetSymbolAddress((void**)&d_rank1,  g_rank1);
    float* d_h1;      cudaGetSymbolAddress((void**)&d_h1,     g_h1);
    float* d_h2;      cudaGetSymbolAddress((void**)&d_h2,     g_h2);

    /* CSR build */
    k_zero_deg<<<NTOT / 256, 256>>>();
    k_hist<<<NE / 256, 256>>>(dst);
    k_scan<<<1, 1024>>>();
    k_scatter<<<NE / 256, 256>>>(src, dst);

    /* layer 1 */
    k_conv1<<<C1GRID, 256>>>(x, W1rel, b1, W1root, p1w);
    k_pool_readout<<<NB, 1024>>>(d_logit1, (const int*)nullptr, (const int*)nullptr,
                                 p1w, d_kept1, d_scale1, d_rank1,
                                 d_h1, out, 1.0f / (float)KP1, 0, KP1);

    /* layer 2 */
    k_gather2<<<NTOT / 8, 256>>>();
    k_gemm2<<<NTOT / G2M, 256>>>(W2rel, b2, W2root, p2w);
    k_pool_readout<<<NB, 1024>>>(d_logit2, d_kept1, d_rank1,
                                 p2w, (int*)nullptr, (float*)nullptr, (int*)nullptr,
                                 d_h2, out, 1.0f / (float)KP2, 1, KP2);
}

// round 16
// speedup vs baseline: 2.7330x; 1.2191x over previous
#include <cuda_runtime.h>
#include <math.h>

#define NB   64
#define NN   1024
#define FIN  14
#define NH   128
#define NTOT (NB*NN)        /* 65536 */
#define NE   (NTOT*8)       /* 524288 */
#define EPG  8192           /* edges per graph (exact: NN*DEG) */
#define KP1  820
#define KP2  656

/* ---------------- scratch (device globals; no allocs allowed) ---------------- */
__device__ __align__(16) int      g_rows[NTOT + 16];
__device__ int                    g_esrc[NE];
__device__ __align__(16) float    g_h1[NTOT * NH];
__device__ __align__(16) float    g_agg2[NTOT * NH];
__device__ __align__(16) float    g_h2[NTOT * NH];
__device__ float                  g_logit1[NTOT];
__device__ float                  g_logit2[NTOT];
__device__ float                  g_scale1[NTOT];
__device__ int                    g_kept1[NTOT];
__device__ int                    g_rank1[NTOT];

/* HW tanh: tanh.approx.f32 (MUFU.TANH) — matches the reference bit-for-bit. */
__device__ __forceinline__ float tanh_hw(float x) {
    float y;
    asm("tanh.approx.f32 %0, %1;" : "=f"(y) : "f"(x));
    return y;
}

/* TF32 operand rounding (RNA) — cuBLAS convention for f32 tensor-core GEMM */
__device__ __forceinline__ unsigned tf32u(float a) {
    unsigned r;
    asm("cvt.rna.tf32.f32 %0, %1;" : "=r"(r) : "f"(a));
    return r;
}

/* ---- fused per-graph CSR build: smem hist + scan + scatter (1 kernel) ----
   Each graph's 8192 edges are contiguous; dst in [g*NN,(g+1)*NN).
   Global row base for graph g is exactly g*EPG.                          ---- */
__global__ void __launch_bounds__(1024)
k_csr(const int* __restrict__ src, const int* __restrict__ dst) {
    __shared__ int cnt[NN];
    __shared__ int pref[NN];

    int g = blockIdx.x, t = threadIdx.x;
    int ebase = g * EPG;
    int vbase = g * NN;

    cnt[t] = 0;
    __syncthreads();

    int dl[8], sl[8];
#pragma unroll
    for (int q = 0; q < 8; q++) {
        int e = ebase + q * 1024 + t;
        dl[q] = dst[e] - vbase;
        sl[q] = src[e];
        atomicAdd(&cnt[dl[q]], 1);
    }
    __syncthreads();

    int v = cnt[t];
    pref[t] = v;
    __syncthreads();
    for (int off = 1; off < 1024; off <<= 1) {
        int x = 0;
        if (t >= off) x = pref[t - off];
        __syncthreads();
        if (t >= off) pref[t] += x;
        __syncthreads();
    }
    int excl = pref[t] - v;
    g_rows[vbase + t] = ebase + excl;
    cnt[t] = excl;                       /* reuse as scatter cursor */
    __syncthreads();

#pragma unroll
    for (int q = 0; q < 8; q++) {
        int p = atomicAdd(&cnt[dl[q]], 1);
        g_esrc[ebase + p] = sl[q];
    }
    if (g == NB - 1 && t == 0) g_rows[NTOT] = NE;
}

/* ---- conv1: grid-stride, warp per node, MLP-4 gather, pure fp32 ---- */
#define C1GRID 1184
__global__ void __launch_bounds__(256)
k_conv1(const float* __restrict__ x,
        const float* __restrict__ W1rel, const float* __restrict__ b1,
        const float* __restrict__ W1root, const float* __restrict__ p1w) {
    __shared__ float sWrel[NH * FIN];
    __shared__ float sWroot[NH * FIN];
    __shared__ float sb[NH];
    __shared__ float spw[NH];
    __shared__ float sAgg[8][FIN];
    __shared__ float sXv[8][FIN];

    int tid = threadIdx.x;
    for (int i = tid; i < NH * FIN; i += 256) {
        sWrel[i]  = W1rel[i];
        sWroot[i] = W1root[i];
    }
    if (tid < NH) { sb[tid] = b1[tid]; spw[tid] = p1w[tid]; }
    __syncthreads();

    int w    = tid >> 5;
    int lane = tid & 31;

    for (int blk = blockIdx.x; blk < NTOT / 8; blk += C1GRID) {
        int v = blk * 8 + w;
        int rs = g_rows[v], re = g_rows[v + 1];
        if (lane < FIN) {
            float a0 = 0.f, a1 = 0.f, a2 = 0.f, a3 = 0.f;
            int i = rs;
            for (; i + 3 < re; i += 4) {
                int s0 = g_esrc[i];
                int s1 = g_esrc[i + 1];
                int s2 = g_esrc[i + 2];
                int s3 = g_esrc[i + 3];
                a0 += x[s0 * FIN + lane];
                a1 += x[s1 * FIN + lane];
                a2 += x[s2 * FIN + lane];
                a3 += x[s3 * FIN + lane];
            }
            for (; i < re; i++) a0 += x[g_esrc[i] * FIN + lane];
            sAgg[w][lane] = (a0 + a1) + (a2 + a3);
            sXv[w][lane]  = x[v * FIN + lane];
        }
        __syncwarp();

        float lp = 0.f;
        float hj[4];
#pragma unroll
        for (int jj = 0; jj < 4; jj++) {
            int j = lane * 4 + jj;
            float acc = sb[j];
#pragma unroll
            for (int k = 0; k < FIN; k++)
                acc += sAgg[w][k] * sWrel[j * FIN + k] + sXv[w][k] * sWroot[j * FIN + k];
            acc = fmaxf(acc, 0.f);
            hj[jj] = acc;
            lp += acc * spw[j];
        }
        *(float4*)&g_h1[v * NH + lane * 4] = make_float4(hj[0], hj[1], hj[2], hj[3]);
#pragma unroll
        for (int o = 16; o > 0; o >>= 1) lp += __shfl_xor_sync(0xffffffffu, lp, o);
        if (lane == 0) g_logit1[v] = lp;
        __syncwarp();
    }
}

/* ------- per-graph top-K + FUSED readout (semantics from R12) ------- */
__device__ __forceinline__ bool pair_before(float va, int ia, float vb, int ib) {
    return (va > vb) || (va == vb && ia < ib);
}

__global__ void __launch_bounds__(1024)
k_pool_readout(const float* __restrict__ logitArr, const int* __restrict__ valid,
               const int* __restrict__ keyIn, const float* __restrict__ w,
               int* __restrict__ keptOut, float* __restrict__ scaleOut,
               int* __restrict__ rankOut,
               const float* __restrict__ h, float* __restrict__ out,
               float invK, int accumulate, int K) {
    __shared__ float sv[NN];
    __shared__ int   si[NN];
    __shared__ float red[128];
    __shared__ float snorm;
    __shared__ float ksc[NN];
    __shared__ int   kkp[NN];
    __shared__ float rsum[8][128];
    __shared__ float rmax[8][128];

    int t = threadIdx.x, g = blockIdx.x;

    if (t < 128) { float w0 = w[t]; red[t] = w0 * w0; }
    __syncthreads();
    if (t < 64) red[t] += red[t + 64];
    __syncthreads();
    if (t < 32) {
        float s = red[t] + red[t + 32];
#pragma unroll
        for (int o = 16; o > 0; o >>= 1) s += __shfl_xor_sync(0xffffffffu, s, o);
        if (t == 0) snorm = __fsqrt_rn(s);
    }
    __syncthreads();

    int orig = g * NN + t;
    float scv = -3.0f;
    int   key;
    if (valid == nullptr || valid[orig]) {
        scv = tanh_hw(__fdiv_rn(logitArr[orig], snorm));
        key = keyIn ? keyIn[orig] : t;
    } else {
        key = 500000 + t;
    }
    sv[t] = scv;
    si[t] = key * 2048 + t;
    __syncthreads();

    for (int k = 2; k <= NN; k <<= 1) {
        for (int j = k >> 1; j > 0; j >>= 1) {
            int ixj = t ^ j;
            if (ixj > t) {
                float va = sv[t], vb = sv[ixj];
                int   ia = si[t], ib = si[ixj];
                bool up = ((t & k) == 0);
                bool swp = up ? pair_before(vb, ib, va, ia)
                              : pair_before(va, ia, vb, ib);
                if (swp) { sv[t] = vb; si[t] = ib; sv[ixj] = va; si[ixj] = ia; }
            }
            __syncthreads();
        }
    }

    int slot = si[t] & 2047;
    int kp   = (t < K) ? 1 : 0;
    float sc = kp ? sv[t] : 0.f;
    kkp[slot] = kp;
    ksc[slot] = sc;
    if (keptOut)  keptOut[g * NN + slot]  = kp;
    if (scaleOut) scaleOut[g * NN + slot] = sc;
    if (rankOut)  rankOut[g * NN + slot]  = t;
    __syncthreads();

    int sub = t >> 7;
    int j   = t & 127;
    float sum = 0.f, mx = -INFINITY;
    int v0 = sub * 128;
#pragma unroll 4
    for (int v = v0; v < v0 + 128; v++) {
        if (kkp[v]) {
            float hv = h[(g * NN + v) * NH + j] * ksc[v];
            sum += hv;
            mx = fmaxf(mx, hv);
        }
    }
    rsum[sub][j] = sum;
    rmax[sub][j] = mx;
    __syncthreads();

    if (t < 128) {
        float s = 0.f, m = -INFINITY;
#pragma unroll
        for (int i = 0; i < 8; i++) {
            s += rsum[i][t];
            m = fmaxf(m, rmax[i][t]);
        }
        float o0 = s * invK;
        if (accumulate) {
            out[g * 256 + t]       += o0;
            out[g * 256 + 128 + t] += m;
        } else {
            out[g * 256 + t]       = o0;
            out[g * 256 + 128 + t] = m;
        }
    }
}

/* ---------------- conv2 aggregation gather, MLP-4 (fp32) ---------------- */
__global__ void __launch_bounds__(256)
k_gather2() {
    int tid  = threadIdx.x;
    int w    = tid >> 5;
    int lane = tid & 31;
    int v    = blockIdx.x * 8 + w;
    if (!g_kept1[v]) return;
    int rs = g_rows[v], re = g_rows[v + 1];
    int l4 = lane * 4;
    float4 a0 = make_float4(0.f, 0.f, 0.f, 0.f);
    float4 a1 = make_float4(0.f, 0.f, 0.f, 0.f);
    float4 a2 = make_float4(0.f, 0.f, 0.f, 0.f);
    float4 a3 = make_float4(0.f, 0.f, 0.f, 0.f);
    int i = rs;
    for (; i + 3 < re; i += 4) {
        int s0 = g_esrc[i];
        int s1 = g_esrc[i + 1];
        int s2 = g_esrc[i + 2];
        int s3 = g_esrc[i + 3];
        float c0 = g_scale1[s0];
        float c1 = g_scale1[s1];
        float c2 = g_scale1[s2];
        float c3 = g_scale1[s3];
        if (c0 != 0.f) {
            float4 hv = *(const float4*)&g_h1[s0 * NH + l4];
            a0.x += hv.x * c0; a0.y += hv.y * c0;
            a0.z += hv.z * c0; a0.w += hv.w * c0;
        }
        if (c1 != 0.f) {
            float4 hv = *(const float4*)&g_h1[s1 * NH + l4];
            a1.x += hv.x * c1; a1.y += hv.y * c1;
            a1.z += hv.z * c1; a1.w += hv.w * c1;
        }
        if (c2 != 0.f) {
            float4 hv = *(const float4*)&g_h1[s2 * NH + l4];
            a2.x += hv.x * c2; a2.y += hv.y * c2;
            a2.z += hv.z * c2; a2.w += hv.w * c2;
        }
        if (c3 != 0.f) {
            float4 hv = *(const float4*)&g_h1[s3 * NH + l4];
            a3.x += hv.x * c3; a3.y += hv.y * c3;
            a3.z += hv.z * c3; a3.w += hv.w * c3;
        }
    }
    for (; i < re; i++) {
        int s0 = g_esrc[i];
        float c0 = g_scale1[s0];
        if (c0 != 0.f) {
            float4 hv = *(const float4*)&g_h1[s0 * NH + l4];
            a0.x += hv.x * c0; a0.y += hv.y * c0;
            a0.z += hv.z * c0; a0.w += hv.w * c0;
        }
    }
    a0.x = (a0.x + a1.x) + (a2.x + a3.x);
    a0.y = (a0.y + a1.y) + (a2.y + a3.y);
    a0.z = (a0.z + a1.z) + (a2.z + a3.z);
    a0.w = (a0.w + a1.w) + (a2.w + a3.w);
    *(float4*)&g_agg2[v * NH + l4] = a0;
}

/* ---- conv2 GEMM: TF32 tensor cores (mma.m16n8k8) + fused logit2 ---- */
#define G2M  128
#define G2K  32
#define KSTR 36
__global__ void __launch_bounds__(256, 2)
k_gemm2(const float* __restrict__ W2rel, const float* __restrict__ b2,
        const float* __restrict__ W2root, const float* __restrict__ p2w) {
    __shared__ __align__(16) unsigned As[G2M * KSTR];
    __shared__ __align__(16) unsigned Ws[G2M * KSTR];
    __shared__ float sb2[NH];
    __shared__ float sp2[NH];
    __shared__ float slp[G2M][2];

    int tid  = threadIdx.x;
    int m0   = blockIdx.x * G2M;
    int warp = tid >> 5;
    int lane = tid & 31;
    int gq   = lane >> 2;
    int tg   = lane & 3;
    int wm   = warp >> 1;
    int wn   = warp & 1;
    int rbw  = wm * 32;
    int cbw  = wn * 64;

    if (tid < NH) { sb2[tid] = b2[tid]; sp2[tid] = p2w[tid]; }

    float d[2][8][4];
#pragma unroll
    for (int mt = 0; mt < 2; mt++)
#pragma unroll
        for (int nt = 0; nt < 8; nt++)
#pragma unroll
            for (int q = 0; q < 4; q++) d[mt][nt][q] = 0.f;

    for (int kc = 0; kc < 2 * NH; kc += G2K) {
#pragma unroll
        for (int r = 0; r < 4; r++) {
            int id  = tid + r * 256;
            int row = id >> 3;
            int k4  = id & 7;
            int kk  = kc + k4 * 4;
            int node = m0 + row;
            float4 val;
            if (kk < NH) {
                val = *(const float4*)&g_agg2[node * NH + kk];
            } else {
                float sc = g_kept1[node] ? g_scale1[node] : 0.f;
                float4 hh = *(const float4*)&g_h1[node * NH + (kk - NH)];
                val = make_float4(hh.x * sc, hh.y * sc, hh.z * sc, hh.w * sc);
            }
            unsigned* p = &As[row * KSTR + k4 * 4];
            p[0] = tf32u(val.x); p[1] = tf32u(val.y);
            p[2] = tf32u(val.z); p[3] = tf32u(val.w);
        }
#pragma unroll
        for (int r = 0; r < 4; r++) {
            int id  = tid + r * 256;
            int col = id >> 3;
            int k4  = id & 7;
            int kk  = kc + k4 * 4;
            const float* Wsrc = (kk < NH) ? W2rel : W2root;
            int kw = (kk < NH) ? kk : (kk - NH);
            float4 val = *(const float4*)&Wsrc[col * NH + kw];
            unsigned* p = &Ws[col * KSTR + k4 * 4];
            p[0] = tf32u(val.x); p[1] = tf32u(val.y);
            p[2] = tf32u(val.z); p[3] = tf32u(val.w);
        }
        __syncthreads();

#pragma unroll
        for (int ks = 0; ks < 4; ks++) {
            int kb = ks * 8;
            unsigned b0[8], b1[8];
#pragma unroll
            for (int nt = 0; nt < 8; nt++) {
                int cb = cbw + nt * 8;
                b0[nt] = Ws[(cb + gq) * KSTR + kb + tg];
                b1[nt] = Ws[(cb + gq) * KSTR + kb + tg + 4];
            }
#pragma unroll
            for (int mt = 0; mt < 2; mt++) {
                int rb = rbw + mt * 16;
                unsigned a0 = As[(rb + gq) * KSTR + kb + tg];
                unsigned a1 = As[(rb + gq + 8) * KSTR + kb + tg];
                unsigned a2 = As[(rb + gq) * KSTR + kb + tg + 4];
                unsigned a3 = As[(rb + gq + 8) * KSTR + kb + tg + 4];
#pragma unroll
                for (int nt = 0; nt < 8; nt++) {
                    asm volatile(
                        "mma.sync.aligned.m16n8k8.row.col.f32.tf32.tf32.f32 "
                        "{%0,%1,%2,%3}, {%4,%5,%6,%7}, {%8,%9}, {%0,%1,%2,%3};"
                        : "+f"(d[mt][nt][0]), "+f"(d[mt][nt][1]),
                          "+f"(d[mt][nt][2]), "+f"(d[mt][nt][3])
                        : "r"(a0), "r"(a1), "r"(a2), "r"(a3),
                          "r"(b0[nt]), "r"(b1[nt]));
                }
            }
        }
        __syncthreads();
    }

#pragma unroll
    for (int mt = 0; mt < 2; mt++) {
        int r0 = rbw + mt * 16 + gq;
        int r1 = r0 + 8;
        float lp0 = 0.f, lp1 = 0.f;
#pragma unroll
        for (int nt = 0; nt < 8; nt++) {
            int c0 = cbw + nt * 8 + 2 * tg;
            int c1 = c0 + 1;
            float v00 = fmaxf(d[mt][nt][0] + sb2[c0], 0.f);
            float v01 = fmaxf(d[mt][nt][1] + sb2[c1], 0.f);
            float v10 = fmaxf(d[mt][nt][2] + sb2[c0], 0.f);
            float v11 = fmaxf(d[mt][nt][3] + sb2[c1], 0.f);
            *(float2*)&g_h2[(m0 + r0) * NH + c0] = make_float2(v00, v01);
            *(float2*)&g_h2[(m0 + r1) * NH + c0] = make_float2(v10, v11);
            lp0 += v00 * sp2[c0] + v01 * sp2[c1];
            lp1 += v10 * sp2[c0] + v11 * sp2[c1];
        }
        lp0 += __shfl_xor_sync(0xffffffffu, lp0, 1);
        lp0 += __shfl_xor_sync(0xffffffffu, lp0, 2);
        lp1 += __shfl_xor_sync(0xffffffffu, lp1, 1);
        lp1 += __shfl_xor_sync(0xffffffffu, lp1, 2);
        if (tg == 0) {
            slp[r0][wn] = lp0;
            slp[r1][wn] = lp1;
        }
    }
    __syncthreads();

    if (tid < G2M) {
        int node = m0 + tid;
        if (g_kept1[node]) g_logit2[node] = slp[tid][0] + slp[tid][1];
    }
}

/* ---------------- launch ---------------- */
extern "C" void kernel_launch(void* const* d_in, const int* in_sizes, int n_in,
                              void* d_out, int out_size) {
    const float* x      = (const float*)d_in[0];
    const int*   ei     = (const int*)d_in[1];
    /* d_in[2] = batch (unused) */
    const float* W1rel  = (const float*)d_in[3];
    const float* b1     = (const float*)d_in[4];
    const float* W1root = (const float*)d_in[5];
    const float* p1w    = (const float*)d_in[6];
    const float* W2rel  = (const float*)d_in[7];
    const float* b2     = (const float*)d_in[8];
    const float* W2root = (const float*)d_in[9];
    const float* p2w    = (const float*)d_in[10];
    float* out = (float*)d_out;

    const int* src = ei;
    const int* dst = ei + NE;

    float* d_logit1;  cudaGetSymbolAddress((void**)&d_logit1, g_logit1);
    float* d_logit2;  cudaGetSymbolAddress((void**)&d_logit2, g_logit2);
    float* d_scale1;  cudaGetSymbolAddress((void**)&d_scale1, g_scale1);
    int*   d_kept1;   cudaGetSymbolAddress((void**)&d_kept1,  g_kept1);
    int*   d_rank1;   cudaGetSymbolAddress((void**)&d_rank1,  g_rank1);
    float* d_h1;      cudaGetSymbolAddress((void**)&d_h1,     g_h1);
    float* d_h2;      cudaGetSymbolAddress((void**)&d_h2,     g_h2);

    /* CSR build: one fused per-graph kernel */
    k_csr<<<NB, 1024>>>(src, dst);

    /* layer 1 */
    k_conv1<<<C1GRID, 256>>>(x, W1rel, b1, W1root, p1w);
    k_pool_readout<<<NB, 1024>>>(d_logit1, (const int*)nullptr, (const int*)nullptr,
                                 p1w, d_kept1, d_scale1, d_rank1,
                                 d_h1, out, 1.0f / (float)KP1, 0, KP1);

    /* layer 2 */
    k_gather2<<<NTOT / 8, 256>>>();
    k_gemm2<<<NTOT / G2M, 256>>>(W2rel, b2, W2root, p2w);
    k_pool_readout<<<NB, 1024>>>(d_logit2, d_kept1, d_rank1,
                                 p2w, (int*)nullptr, (float*)nullptr, (int*)nullptr,
                                 d_h2, out, 1.0f / (float)KP2, 1, KP2);
}